// round 11
// baseline (speedup 1.0000x reference)
#include <cuda_runtime.h>
#include <cuda_bf16.h>
#include <cuda_fp16.h>
#include <cuda_fp8.h>
#include <cstdint>

#define NROWS 4096
#define DIM   512
#define NCLS  100000
#define NBM   32
#define NBN   368            // tensor col tiles per strip: 368*256 = 94208 cols
#define NFB   362            // FMA 16-col blocks: 362*16 = 5792 -> total 100000
#define FCOL0 94208
#define NTILES (NBM * NBN)   // 11776
#define GRID  148
#define S_SCALE 30.0f
#define MARGIN  0.4f
#define XS 8.0f              // fp8 scale for xn
#define WS 32.0f             // scale for W (fp8 and fp16 copies)
#define EXPS (S_SCALE / (XS * WS))

// ---------------- scratch (module-static device memory: allowed) ------------
__device__ __align__(128) uint8_t  g_WB8[(size_t)NCLS * DIM];    // e4m3 W*32
__device__ __align__(128) uint8_t  g_xn8[(size_t)NROWS * DIM];   // e4m3 xn*8
__device__ __align__(128) uint32_t g_WF16[(size_t)NFB * 256 * 16]; // f16x2(k,k+1)*W*32
__device__ float g_rowsum[NROWS];
__device__ float g_target[NROWS];
__device__ int   g_done;

// ---------------- PTX helpers (sm_80/89-era, safe on sm_103) ----------------
__device__ __forceinline__ uint32_t smem_u32(const void* p) {
    uint32_t a;
    asm("{ .reg .u64 t; cvta.to.shared.u64 t, %1; cvt.u32.u64 %0, t; }" : "=r"(a) : "l"(p));
    return a;
}
#define CP_ASYNC16(dst, src) \
    asm volatile("cp.async.cg.shared.global [%0], [%1], 16;" :: "r"(dst), "l"(src) : "memory")
#define CP_COMMIT()  asm volatile("cp.async.commit_group;" ::: "memory")
#define CP_WAIT0()   asm volatile("cp.async.wait_group 0;" ::: "memory")
#define CP_WAIT1()   asm volatile("cp.async.wait_group 1;" ::: "memory")
#define SCHED_FENCE() asm volatile("" ::: "memory")

__device__ __forceinline__ void ldsm4(uint32_t* r, uint32_t addr) {
    asm volatile("ldmatrix.sync.aligned.m8n8.x4.shared.b16 {%0,%1,%2,%3}, [%4];"
                 : "=r"(r[0]), "=r"(r[1]), "=r"(r[2]), "=r"(r[3]) : "r"(addr));
}
__device__ __forceinline__ void mma_fp8_h(uint32_t* c, const uint32_t* a,
                                          uint32_t b0, uint32_t b1) {
    asm volatile("mma.sync.aligned.m16n8k32.row.col.f16.e4m3.e4m3.f16 "
                 "{%0,%1}, {%2,%3,%4,%5}, {%6,%7}, {%0,%1};"
                 : "+r"(c[0]), "+r"(c[1])
                 : "r"(a[0]), "r"(a[1]), "r"(a[2]), "r"(a[3]), "r"(b0), "r"(b1));
}
__device__ __forceinline__ uint32_t pack4_e4m3(float a0, float a1, float a2, float a3) {
    __nv_fp8x2_e4m3 lo(make_float2(a0, a1));
    __nv_fp8x2_e4m3 hi(make_float2(a2, a3));
    return (uint32_t)lo.__x | ((uint32_t)hi.__x << 16);
}
__device__ __forceinline__ float2 h2f2(uint32_t r) {
    return __half22float2(*reinterpret_cast<__half2*>(&r));
}

// ---------------- tiling (pitches in BYTES) -----------------------------------
#define BM 128
#define BN 256
#define CHUNK_B 128
#define NCHUNK  4
#define APITCH 528           // 132 words == 4 mod 32 (ldsm conflict-free)
#define BPITCH 144           // 36 words  == 4 mod 32

#define A_BYTES       (BM * APITCH)                  // 67584
#define B_STAGE_BYTES (BN * BPITCH)                  // 36864
#define B_OFF         A_BYTES
#define FB_OFF        (B_OFF + 2 * B_STAGE_BYTES)    // 141312; 2 x 4KB fma stages
#define SMEM_BYTES    (FB_OFF + 8192)                // 149504

// ======================= kernel 1: prep ======================================
__device__ __forceinline__ float block_reduce_128(float v, float* sbuf, int tid) {
    #pragma unroll
    for (int o = 16; o > 0; o >>= 1) v += __shfl_xor_sync(0xffffffffu, v, o);
    if ((tid & 31) == 0) sbuf[tid >> 5] = v;
    __syncthreads();
    float r = sbuf[0] + sbuf[1] + sbuf[2] + sbuf[3];
    __syncthreads();
    return r;
}

__global__ void prep_kernel(const float* __restrict__ x,
                            const int* __restrict__ labels_raw,
                            const float* __restrict__ W) {
    __shared__ float sbuf[4];
    const int tid = threadIdx.x;
    if (blockIdx.x < NROWS) {
        const int row = blockIdx.x;
        const float* xr = x + (size_t)row * DIM;
        float v[4]; float ss = 0.f;
        #pragma unroll
        for (int j = 0; j < 4; j++) { v[j] = xr[tid + 128*j]; ss += v[j]*v[j]; }
        ss = block_reduce_128(ss, sbuf, tid);
        float inv = rsqrtf(ss);
        #pragma unroll
        for (int j = 0; j < 4; j++)
            g_xn8[(size_t)row * DIM + tid + 128*j] =
                __nv_fp8_e4m3(v[j] * inv * XS).__x;

        bool is64 = (labels_raw[1] == 0 && labels_raw[3] == 0 &&
                     labels_raw[5] == 0 && labels_raw[7] == 0);
        int lab = is64 ? labels_raw[2*row] : labels_raw[row];
        const float* w = W + (size_t)lab * DIM;
        float dot = 0.f;
        #pragma unroll
        for (int j = 0; j < 4; j++) dot += v[j] * w[tid + 128*j];
        dot = block_reduce_128(dot, sbuf, tid);
        if (tid == 0) { g_target[row] = dot * inv; g_rowsum[row] = 0.f; }
    } else if (blockIdx.x < NROWS + 25000) {
        if (blockIdx.x == NROWS && tid == 0) g_done = 0;
        const size_t base = ((size_t)(blockIdx.x - NROWS) * 128 + tid) * 16;
        const float4* src = reinterpret_cast<const float4*>(W + base);
        float4 v0 = src[0], v1 = src[1], v2 = src[2], v3 = src[3];
        uint4 o;
        o.x = pack4_e4m3(v0.x*WS, v0.y*WS, v0.z*WS, v0.w*WS);
        o.y = pack4_e4m3(v1.x*WS, v1.y*WS, v1.z*WS, v1.w*WS);
        o.z = pack4_e4m3(v2.x*WS, v2.y*WS, v2.z*WS, v2.w*WS);
        o.w = pack4_e4m3(v3.x*WS, v3.y*WS, v3.z*WS, v3.w*WS);
        *reinterpret_cast<uint4*>(g_WB8 + base) = o;
    } else {
        // f16x2-packed W for the FMA side path: block b covers 16 cols
        const int b = blockIdx.x - NROWS - 25000;   // 0..NFB-1
        #pragma unroll
        for (int i = 0; i < 32; i++) {
            int idx = tid + 128 * i;                // 0..4095
            int k2 = idx >> 4, c = idx & 15;
            int col = FCOL0 + b * 16 + c;
            const float* wp = W + (size_t)col * DIM + 2 * k2;
            __half2 h = __floats2half2_rn(wp[0] * WS, wp[1] * WS);
            g_WF16[((size_t)b * 256 + k2) * 16 + c] = *reinterpret_cast<uint32_t*>(&h);
        }
    }
}

// ======================= kernel 2: fp8-mma + HFMA2 side path =================
__device__ __forceinline__ void issue_b_chunk(uint32_t bs_dst, int bn, int k0, int tid) {
    #pragma unroll
    for (int i = 0; i < 8; i++) {
        int v = tid + 256 * i;
        int r = v >> 3, kv = v & 7;
        const void* src = g_WB8 + ((size_t)(bn * BN + r) * DIM + k0 + kv * 16);
        CP_ASYNC16(bs_dst + r * BPITCH + kv * 16, src);
    }
}
__device__ __forceinline__ void issue_fb_chunk(uint32_t dst, int bn, int jc, int tid) {
    const void* src = g_WF16 + ((size_t)bn * 256 + jc * 64) * 16 + tid * 4;
    CP_ASYNC16(dst + tid * 16, src);
}

__global__ void __launch_bounds__(256, 1) gemm_exp_kernel(float* __restrict__ out) {
    extern __shared__ __align__(16) char smem[];
    const uint32_t sb = smem_u32(smem);
    const int tid = threadIdx.x, wid = tid >> 5, lane = tid & 31;
    const int wm = wid & 1, wn = wid >> 1;
    const int cta = blockIdx.x;
    const int t0 = (cta * NTILES) / GRID;
    const int t1 = ((cta + 1) * NTILES) / GRID;

    const int lrow = lane & 15, lk16 = (lane >> 4) * 16;
    const uint32_t a_lane = sb + (wm * 64 + lrow) * APITCH + lk16;
    const uint32_t b_lane = sb + B_OFF + (wn * 64 + lrow) * BPITCH + lk16;
    // FMA side path lane mapping: 2 threads per row, 8 cols each
    const int frow = tid >> 1;
    const uint32_t fa_base = sb + frow * APITCH;
    const uint32_t fb_base = sb + FB_OFF + (tid & 1) * 32;

    int t = t0;
    while (t < t1) {
        const int bm = t / NBN;
        const int bn0 = t - bm * NBN;
        const int seg_end = min(t1, (bm + 1) * NBN);
        const int total = (seg_end - t) * NCHUNK;

        __syncthreads();
        const uint8_t* xa = g_xn8 + (size_t)bm * BM * DIM;
        #pragma unroll 4
        for (int i = 0; i < 16; i++) {
            int v = tid + 256 * i;
            int r = v >> 5, kv = v & 31;
            CP_ASYNC16(sb + r * APITCH + kv * 16, xa + ((size_t)r * DIM + kv * 16));
        }
        CP_COMMIT();
        issue_b_chunk(sb + B_OFF, bn0, 0, tid);
        if (bn0 < NFB) issue_fb_chunk(sb + FB_OFF, bn0, 0, tid);
        CP_COMMIT();

        uint32_t acc[4][8][2];
        #pragma unroll
        for (int fm = 0; fm < 4; fm++)
            #pragma unroll
            for (int q = 0; q < 8; q++) { acc[fm][q][0] = 0u; acc[fm][q][1] = 0u; }
        __half2 facc[8];
        #pragma unroll
        for (int c = 0; c < 8; c++) facc[c] = __float2half2_rn(0.f);
        float rsum[8] = {0.f,0.f,0.f,0.f,0.f,0.f,0.f,0.f};
        float frsum = 0.f;

        for (int j = 0; j < total; j++) {
            __syncthreads();
            int jn = j + 1;
            if (jn < total) {
                int bnn = bn0 + (jn >> 2), jcn = jn & 3;
                issue_b_chunk(sb + B_OFF + (jn & 1) * B_STAGE_BYTES,
                              bnn, jcn * CHUNK_B, tid);
                if (bnn < NFB)
                    issue_fb_chunk(sb + FB_OFF + (jn & 1) * 4096, bnn, jcn, tid);
                CP_COMMIT();
                CP_WAIT1();
            } else {
                CP_WAIT0();
            }
            __syncthreads();

            const int jc = j & 3;
            const int bn_cur = bn0 + (j >> 2);
            const bool fma_on = (bn_cur < NFB);
            const uint32_t bch = b_lane + (j & 1) * B_STAGE_BYTES;
            const uint32_t ach = a_lane + jc * CHUNK_B;

            // ---- tensor region (tight live set: acc + Af/Bf) ----
            #pragma unroll
            for (int ks = 0; ks < 4; ks++) {
                uint32_t Af[4][4], Bf[4][4];
                #pragma unroll
                for (int fm = 0; fm < 4; fm++)
                    ldsm4(Af[fm], ach + fm * 16 * APITCH + ks * 32);
                #pragma unroll
                for (int f = 0; f < 4; f++)
                    ldsm4(Bf[f], bch + f * 16 * BPITCH + ks * 32);
                #pragma unroll
                for (int fm = 0; fm < 4; fm++)
                    #pragma unroll
                    for (int f = 0; f < 4; f++) {
                        mma_fp8_h(acc[fm][2*f],   Af[fm], Bf[f][0], Bf[f][2]);
                        mma_fp8_h(acc[fm][2*f+1], Af[fm], Bf[f][1], Bf[f][3]);
                    }
            }

            // ---- HFMA2 side region (separate live range; fenced) ----
            if (fma_on) {
                SCHED_FENCE();
                const uint32_t fa = fa_base + jc * CHUNK_B;
                const uint32_t fb = fb_base + (j & 1) * 4096;
                #pragma unroll 4
                for (int k2 = 0; k2 < 64; k2++) {
                    uint16_t a8;
                    asm volatile("ld.shared.u16 %0, [%1];"
                                 : "=h"(a8) : "r"(fa + k2 * 2));
                    uint32_t a2;
                    asm volatile("cvt.rn.f16x2.e4m3x2 %0, %1;" : "=r"(a2) : "h"(a8));
                    __half2 av = *reinterpret_cast<__half2*>(&a2);
                    uint32_t b0,b1,b2,b3,b4,b5,b6,b7;
                    uint32_t fba = fb + k2 * 64;
                    asm volatile("ld.shared.v4.u32 {%0,%1,%2,%3}, [%4];"
                                 : "=r"(b0),"=r"(b1),"=r"(b2),"=r"(b3) : "r"(fba));
                    asm volatile("ld.shared.v4.u32 {%0,%1,%2,%3}, [%4];"
                                 : "=r"(b4),"=r"(b5),"=r"(b6),"=r"(b7) : "r"(fba + 16));
                    facc[0] = __hfma2(av, *reinterpret_cast<__half2*>(&b0), facc[0]);
                    facc[1] = __hfma2(av, *reinterpret_cast<__half2*>(&b1), facc[1]);
                    facc[2] = __hfma2(av, *reinterpret_cast<__half2*>(&b2), facc[2]);
                    facc[3] = __hfma2(av, *reinterpret_cast<__half2*>(&b3), facc[3]);
                    facc[4] = __hfma2(av, *reinterpret_cast<__half2*>(&b4), facc[4]);
                    facc[5] = __hfma2(av, *reinterpret_cast<__half2*>(&b5), facc[5]);
                    facc[6] = __hfma2(av, *reinterpret_cast<__half2*>(&b6), facc[6]);
                    facc[7] = __hfma2(av, *reinterpret_cast<__half2*>(&b7), facc[7]);
                }
                SCHED_FENCE();
            }

            // ---- per-tile epilogue ----
            if (jc == 3) {
                #pragma unroll
                for (int fm = 0; fm < 4; fm++) {
                    float s0 = 0.f, s1 = 0.f;
                    #pragma unroll
                    for (int q = 0; q < 8; q++) {
                        float2 f0 = h2f2(acc[fm][q][0]);
                        float2 f1 = h2f2(acc[fm][q][1]);
                        s0 += __expf(EXPS * f0.x) + __expf(EXPS * f0.y);
                        s1 += __expf(EXPS * f1.x) + __expf(EXPS * f1.y);
                        acc[fm][q][0] = 0u; acc[fm][q][1] = 0u;
                    }
                    rsum[2*fm] += s0; rsum[2*fm+1] += s1;
                }
                if (fma_on) {
                    // facc[c] holds the two K-halves of ONE column's dot:
                    // dot = f.x + f.y  ->  one exp per column
                    float fr = 0.f;
                    #pragma unroll
                    for (int c = 0; c < 8; c++) {
                        float2 f = __half22float2(facc[c]);
                        fr += __expf(EXPS * (f.x + f.y));
                        facc[c] = __float2half2_rn(0.f);
                    }
                    frsum += fr;
                }
            }
        }

        // ---- segment flush ----
        #pragma unroll
        for (int k = 0; k < 8; k++) {
            float v = rsum[k];
            v += __shfl_xor_sync(0xffffffffu, v, 1);
            v += __shfl_xor_sync(0xffffffffu, v, 2);
            if ((lane & 3) == 0) {
                int row = bm * BM + wm * 64 + (k >> 1) * 16 + (lane >> 2) + (k & 1) * 8;
                atomicAdd(&g_rowsum[row], v);
            }
        }
        atomicAdd(&g_rowsum[bm * BM + frow], frsum);
        frsum = 0.f;
        t = seg_end;
    }

    // ---- last CTA computes the loss (finalize folded in) ----
    __threadfence();
    __syncthreads();
    __shared__ int slast;
    if (tid == 0) slast = (atomicAdd(&g_done, 1) == GRID - 1) ? 1 : 0;
    __syncthreads();
    if (slast) {
        __threadfence();
        double* sd = reinterpret_cast<double*>(smem);
        double local = 0.0;
        for (int i = tid; i < NROWS; i += 256) {
            float tg  = g_target[i];
            float num = S_SCALE * (tg - MARGIN);
            float denom = __expf(num) + g_rowsum[i] - __expf(S_SCALE * tg);
            local += (double)num - (double)__logf(denom);
        }
        sd[tid] = local;
        __syncthreads();
        for (int s = 128; s > 0; s >>= 1) {
            if (tid < s) sd[tid] += sd[tid + s];
            __syncthreads();
        }
        if (tid == 0) out[0] = (float)(-sd[0] / (double)NROWS);
    }
}

// ======================= launch ==============================================
extern "C" void kernel_launch(void* const* d_in, const int* in_sizes, int n_in,
                              void* d_out, int out_size) {
    const float* x      = (const float*)d_in[0];
    const int*   labels = (const int*)d_in[1];
    const float* W      = (const float*)d_in[2];
    float* out = (float*)d_out;

    cudaFuncSetAttribute(gemm_exp_kernel,
                         cudaFuncAttributeMaxDynamicSharedMemorySize, SMEM_BYTES);

    prep_kernel<<<NROWS + 25000 + NFB, 128>>>(x, labels, W);
    gemm_exp_kernel<<<GRID, 256, SMEM_BYTES>>>(out);
}

// round 12
// speedup vs baseline: 1.4804x; 1.4804x over previous
#include <cuda_runtime.h>
#include <cuda_bf16.h>
#include <cuda_fp16.h>
#include <cuda_fp8.h>
#include <cstdint>

#define NROWS 4096
#define DIM   512
#define NCLS  100000
#define NBM   32
#define NBN   391            // ceil(100000/256)
#define NTILES (NBM * NBN)   // 12512
#define GRID  148
#define THREADS 512
#define S_SCALE 30.0f
#define MARGIN  0.4f
#define XS 8.0f              // fp8 scale for xn
#define WS 32.0f             // fp8 scale for W
#define EXPS (S_SCALE / (XS * WS))

// ---------------- scratch (module-static device memory: allowed) ------------
__device__ __align__(128) uint8_t g_WB8[(size_t)NCLS * DIM];   // e4m3 W*32
__device__ __align__(128) uint8_t g_xn8[(size_t)NROWS * DIM];  // e4m3 xn*8
__device__ float g_rowsum[NROWS];
__device__ float g_target[NROWS];
__device__ int   g_done;

// ---------------- PTX helpers (sm_80/89-era, safe on sm_103) ----------------
__device__ __forceinline__ uint32_t smem_u32(const void* p) {
    uint32_t a;
    asm("{ .reg .u64 t; cvta.to.shared.u64 t, %1; cvt.u32.u64 %0, t; }" : "=r"(a) : "l"(p));
    return a;
}
#define CP_ASYNC16(dst, src) \
    asm volatile("cp.async.cg.shared.global [%0], [%1], 16;" :: "r"(dst), "l"(src) : "memory")
#define CP_COMMIT()  asm volatile("cp.async.commit_group;" ::: "memory")
#define CP_WAIT0()   asm volatile("cp.async.wait_group 0;" ::: "memory")
#define CP_WAIT1()   asm volatile("cp.async.wait_group 1;" ::: "memory")

__device__ __forceinline__ void ldsm4(uint32_t* r, uint32_t addr) {
    asm volatile("ldmatrix.sync.aligned.m8n8.x4.shared.b16 {%0,%1,%2,%3}, [%4];"
                 : "=r"(r[0]), "=r"(r[1]), "=r"(r[2]), "=r"(r[3]) : "r"(addr));
}
__device__ __forceinline__ void mma_fp8_h(uint32_t* c, const uint32_t* a,
                                          uint32_t b0, uint32_t b1) {
    asm volatile("mma.sync.aligned.m16n8k32.row.col.f16.e4m3.e4m3.f16 "
                 "{%0,%1}, {%2,%3,%4,%5}, {%6,%7}, {%0,%1};"
                 : "+r"(c[0]), "+r"(c[1])
                 : "r"(a[0]), "r"(a[1]), "r"(a[2]), "r"(a[3]), "r"(b0), "r"(b1));
}
__device__ __forceinline__ uint32_t pack4_e4m3(float a0, float a1, float a2, float a3) {
    __nv_fp8x2_e4m3 lo(make_float2(a0, a1));
    __nv_fp8x2_e4m3 hi(make_float2(a2, a3));
    return (uint32_t)lo.__x | ((uint32_t)hi.__x << 16);
}
__device__ __forceinline__ float2 h2f2(uint32_t r) {
    return __half22float2(*reinterpret_cast<__half2*>(&r));
}

// ---------------- tiling (pitches in BYTES) -----------------------------------
#define BM 128
#define BN 256
#define CHUNK_B 128
#define NCHUNK  4
#define APITCH 528           // 132 words == 4 mod 32 (ldsm conflict-free)
#define BPITCH 144           // 36 words  == 4 mod 32

#define A_BYTES       (BM * APITCH)                  // 67584
#define B_STAGE_BYTES (BN * BPITCH)                  // 36864
#define B_OFF         A_BYTES
#define SMEM_BYTES    (B_OFF + 2 * B_STAGE_BYTES)    // 141312

// ======================= kernel 1: prep ======================================
__device__ __forceinline__ float block_reduce_128(float v, float* sbuf, int tid) {
    #pragma unroll
    for (int o = 16; o > 0; o >>= 1) v += __shfl_xor_sync(0xffffffffu, v, o);
    if ((tid & 31) == 0) sbuf[tid >> 5] = v;
    __syncthreads();
    float r = sbuf[0] + sbuf[1] + sbuf[2] + sbuf[3];
    __syncthreads();
    return r;
}

__global__ void prep_kernel(const float* __restrict__ x,
                            const int* __restrict__ labels_raw,
                            const float* __restrict__ W) {
    __shared__ float sbuf[4];
    const int tid = threadIdx.x;
    if (blockIdx.x < NROWS) {
        const int row = blockIdx.x;
        const float* xr = x + (size_t)row * DIM;
        float v[4]; float ss = 0.f;
        #pragma unroll
        for (int j = 0; j < 4; j++) { v[j] = xr[tid + 128*j]; ss += v[j]*v[j]; }
        ss = block_reduce_128(ss, sbuf, tid);
        float inv = rsqrtf(ss);
        #pragma unroll
        for (int j = 0; j < 4; j++)
            g_xn8[(size_t)row * DIM + tid + 128*j] =
                __nv_fp8_e4m3(v[j] * inv * XS).__x;

        bool is64 = (labels_raw[1] == 0 && labels_raw[3] == 0 &&
                     labels_raw[5] == 0 && labels_raw[7] == 0);
        int lab = is64 ? labels_raw[2*row] : labels_raw[row];
        const float* w = W + (size_t)lab * DIM;
        float dot = 0.f;
        #pragma unroll
        for (int j = 0; j < 4; j++) dot += v[j] * w[tid + 128*j];
        dot = block_reduce_128(dot, sbuf, tid);
        if (tid == 0) { g_target[row] = dot * inv; g_rowsum[row] = 0.f; }
    } else {
        if (blockIdx.x == NROWS && tid == 0) g_done = 0;
        const size_t base = ((size_t)(blockIdx.x - NROWS) * 128 + tid) * 16;
        const float4* src = reinterpret_cast<const float4*>(W + base);
        float4 v0 = src[0], v1 = src[1], v2 = src[2], v3 = src[3];
        uint4 o;
        o.x = pack4_e4m3(v0.x*WS, v0.y*WS, v0.z*WS, v0.w*WS);
        o.y = pack4_e4m3(v1.x*WS, v1.y*WS, v1.z*WS, v1.w*WS);
        o.z = pack4_e4m3(v2.x*WS, v2.y*WS, v2.z*WS, v2.w*WS);
        o.w = pack4_e4m3(v3.x*WS, v3.y*WS, v3.z*WS, v3.w*WS);
        *reinterpret_cast<uint4*>(g_WB8 + base) = o;
    }
}

// ======================= kernel 2: fp8-mma GEMM + exp rowsum =================
// 148 persistent CTAs, 512 threads / 16 warps.  Warp grid 4(m) x 4(n);
// warp tile 32x64 (acc = 2fm x 8q f16x2 pairs = 32 regs).  4 warps/SMSP for
// latency hiding.  2-stage cp.async pipeline over 128B K-chunks.
__device__ __forceinline__ void issue_b_chunk(uint32_t bs_dst, int bn, int k0, int tid) {
    #pragma unroll
    for (int i = 0; i < 4; i++) {
        int v = tid + THREADS * i;              // 2048 vectors = 256 rows x 8
        int r = v >> 3, kv = v & 7;
        int grow = bn * BN + r; if (grow >= NCLS) grow = NCLS - 1;
        const void* src = g_WB8 + ((size_t)grow * DIM + k0 + kv * 16);
        CP_ASYNC16(bs_dst + r * BPITCH + kv * 16, src);
    }
}

__global__ void __launch_bounds__(THREADS, 1) gemm_exp_kernel(float* __restrict__ out) {
    extern __shared__ __align__(16) char smem[];
    const uint32_t sb = smem_u32(smem);
    const int tid = threadIdx.x, wid = tid >> 5, lane = tid & 31;
    const int wm = wid & 3, wn = wid >> 2;
    const int cta = blockIdx.x;
    const int t0 = (cta * NTILES) / GRID;
    const int t1 = ((cta + 1) * NTILES) / GRID;

    const int lrow = lane & 15, lk16 = (lane >> 4) * 16;
    const uint32_t a_lane = sb + (wm * 32 + lrow) * APITCH + lk16;
    const uint32_t b_lane = sb + B_OFF + (wn * 64 + lrow) * BPITCH + lk16;

    int t = t0;
    while (t < t1) {
        const int bm = t / NBN;
        const int bn0 = t - bm * NBN;
        const int seg_end = min(t1, (bm + 1) * NBN);
        const int total = (seg_end - t) * NCHUNK;

        __syncthreads();   // prior-segment readers done before overwriting SMEM
        const uint8_t* xa = g_xn8 + (size_t)bm * BM * DIM;
        #pragma unroll
        for (int i = 0; i < 8; i++) {
            int v = tid + THREADS * i;          // 4096 vectors = 128 rows x 32
            int r = v >> 5, kv = v & 31;
            CP_ASYNC16(sb + r * APITCH + kv * 16, xa + ((size_t)r * DIM + kv * 16));
        }
        CP_COMMIT();
        issue_b_chunk(sb + B_OFF, bn0, 0, tid);
        CP_COMMIT();

        uint32_t acc[2][8][2];
        #pragma unroll
        for (int fm = 0; fm < 2; fm++)
            #pragma unroll
            for (int q = 0; q < 8; q++) { acc[fm][q][0] = 0u; acc[fm][q][1] = 0u; }
        float rsum[4] = {0.f, 0.f, 0.f, 0.f};

        for (int j = 0; j < total; j++) {
            __syncthreads();
            int jn = j + 1;
            if (jn < total) {
                issue_b_chunk(sb + B_OFF + (jn & 1) * B_STAGE_BYTES,
                              bn0 + (jn >> 2), (jn & 3) * CHUNK_B, tid);
                CP_COMMIT();
                CP_WAIT1();
            } else {
                CP_WAIT0();
            }
            __syncthreads();

            const int jc = j & 3;
            const uint32_t bch = b_lane + (j & 1) * B_STAGE_BYTES;
            const uint32_t ach = a_lane + jc * CHUNK_B;
            #pragma unroll
            for (int ks = 0; ks < 4; ks++) {
                uint32_t Af[2][4], Bf[4][4];
                #pragma unroll
                for (int fm = 0; fm < 2; fm++)
                    ldsm4(Af[fm], ach + fm * 16 * APITCH + ks * 32);
                #pragma unroll
                for (int f = 0; f < 4; f++)
                    ldsm4(Bf[f], bch + f * 16 * BPITCH + ks * 32);
                #pragma unroll
                for (int fm = 0; fm < 2; fm++)
                    #pragma unroll
                    for (int f = 0; f < 4; f++) {
                        mma_fp8_h(acc[fm][2*f],   Af[fm], Bf[f][0], Bf[f][2]);
                        mma_fp8_h(acc[fm][2*f+1], Af[fm], Bf[f][1], Bf[f][3]);
                    }
            }

            // ---- per-tile epilogue: exp on accumulator registers ----
            if (jc == 3) {
                const int bn = bn0 + (j >> 2);
                if (bn != NBN - 1) {
                    #pragma unroll
                    for (int fm = 0; fm < 2; fm++) {
                        float s0 = 0.f, s1 = 0.f;
                        #pragma unroll
                        for (int q = 0; q < 8; q++) {
                            float2 f0 = h2f2(acc[fm][q][0]);
                            float2 f1 = h2f2(acc[fm][q][1]);
                            s0 += __expf(EXPS * f0.x) + __expf(EXPS * f0.y);
                            s1 += __expf(EXPS * f1.x) + __expf(EXPS * f1.y);
                            acc[fm][q][0] = 0u; acc[fm][q][1] = 0u;
                        }
                        rsum[2*fm] += s0; rsum[2*fm+1] += s1;
                    }
                } else {
                    // tail tile: cols [99840, 100096), valid local col < 160
                    const int cb = wn * 64 + (lane & 3) * 2;
                    #pragma unroll
                    for (int fm = 0; fm < 2; fm++) {
                        float s0 = 0.f, s1 = 0.f;
                        #pragma unroll
                        for (int q = 0; q < 8; q++) {
                            int c0 = cb + q * 8;
                            float2 f0 = h2f2(acc[fm][q][0]);
                            float2 f1 = h2f2(acc[fm][q][1]);
                            if (c0 < 160) {
                                s0 += __expf(EXPS * f0.x);
                                s1 += __expf(EXPS * f1.x);
                            }
                            if (c0 + 1 < 160) {
                                s0 += __expf(EXPS * f0.y);
                                s1 += __expf(EXPS * f1.y);
                            }
                            acc[fm][q][0] = 0u; acc[fm][q][1] = 0u;
                        }
                        rsum[2*fm] += s0; rsum[2*fm+1] += s1;
                    }
                }
            }
        }

        // ---- segment flush: quad-reduce, one atomic per row ----
        #pragma unroll
        for (int k = 0; k < 4; k++) {
            float v = rsum[k];
            v += __shfl_xor_sync(0xffffffffu, v, 1);
            v += __shfl_xor_sync(0xffffffffu, v, 2);
            if ((lane & 3) == 0) {
                int row = bm * BM + wm * 32 + (k >> 1) * 16 + (lane >> 2) + (k & 1) * 8;
                atomicAdd(&g_rowsum[row], v);
            }
        }
        t = seg_end;
    }

    // ---- last CTA computes the loss (finalize folded in) ----
    __threadfence();
    __syncthreads();
    __shared__ int slast;
    if (tid == 0) slast = (atomicAdd(&g_done, 1) == GRID - 1) ? 1 : 0;
    __syncthreads();
    if (slast) {
        __threadfence();
        double* sd = reinterpret_cast<double*>(smem);
        double local = 0.0;
        for (int i = tid; i < NROWS; i += THREADS) {
            float tg  = g_target[i];
            float num = S_SCALE * (tg - MARGIN);
            float denom = __expf(num) + g_rowsum[i] - __expf(S_SCALE * tg);
            local += (double)num - (double)__logf(denom);
        }
        sd[tid] = local;
        __syncthreads();
        for (int s = THREADS / 2; s > 0; s >>= 1) {
            if (tid < s) sd[tid] += sd[tid + s];
            __syncthreads();
        }
        if (tid == 0) out[0] = (float)(-sd[0] / (double)NROWS);
    }
}

// ======================= launch ==============================================
extern "C" void kernel_launch(void* const* d_in, const int* in_sizes, int n_in,
                              void* d_out, int out_size) {
    const float* x      = (const float*)d_in[0];
    const int*   labels = (const int*)d_in[1];
    const float* W      = (const float*)d_in[2];
    float* out = (float*)d_out;

    cudaFuncSetAttribute(gemm_exp_kernel,
                         cudaFuncAttributeMaxDynamicSharedMemorySize, SMEM_BYTES);

    prep_kernel<<<NROWS + 25000, 128>>>(x, labels, W);
    gemm_exp_kernel<<<GRID, THREADS, SMEM_BYTES>>>(out);
}

// round 13
// speedup vs baseline: 1.5473x; 1.0452x over previous
#include <cuda_runtime.h>
#include <cuda_bf16.h>
#include <cuda_fp16.h>
#include <cuda_fp8.h>
#include <cstdint>

#define NROWS 4096
#define DIM   512
#define NCLS  100000
#define NBM   32
#define NBN   391            // ceil(100000/256)
#define NTILES (NBM * NBN)   // 12512
#define GRID  148
#define THREADS 512
#define S_SCALE 30.0f
#define MARGIN  0.4f
#define XS 8.0f              // fp8 scale for xn
#define WS 32.0f             // fp8 scale for W
#define EXPS (S_SCALE / (XS * WS))
#define LOG2E 1.4426950408889634f

// ---------------- scratch (module-static device memory: allowed) ------------
__device__ __align__(128) uint8_t g_WB8[(size_t)NCLS * DIM];   // e4m3 W*32
__device__ __align__(128) uint8_t g_xn8[(size_t)NROWS * DIM];  // e4m3 xn*8
__device__ float g_rowsum[NROWS];
__device__ float g_target[NROWS];
__device__ int   g_done;

// ---------------- PTX helpers (sm_80/89-era, safe on sm_103) ----------------
__device__ __forceinline__ uint32_t smem_u32(const void* p) {
    uint32_t a;
    asm("{ .reg .u64 t; cvta.to.shared.u64 t, %1; cvt.u32.u64 %0, t; }" : "=r"(a) : "l"(p));
    return a;
}
#define CP_ASYNC16(dst, src) \
    asm volatile("cp.async.cg.shared.global [%0], [%1], 16;" :: "r"(dst), "l"(src) : "memory")
#define CP_COMMIT()  asm volatile("cp.async.commit_group;" ::: "memory")
#define CP_WAIT0()   asm volatile("cp.async.wait_group 0;" ::: "memory")
#define CP_WAIT1()   asm volatile("cp.async.wait_group 1;" ::: "memory")

__device__ __forceinline__ void ldsm4(uint32_t* r, uint32_t addr) {
    asm volatile("ldmatrix.sync.aligned.m8n8.x4.shared.b16 {%0,%1,%2,%3}, [%4];"
                 : "=r"(r[0]), "=r"(r[1]), "=r"(r[2]), "=r"(r[3]) : "r"(addr));
}
__device__ __forceinline__ void mma_fp8_h(uint32_t* c, const uint32_t* a,
                                          uint32_t b0, uint32_t b1) {
    asm volatile("mma.sync.aligned.m16n8k32.row.col.f16.e4m3.e4m3.f16 "
                 "{%0,%1}, {%2,%3,%4,%5}, {%6,%7}, {%0,%1};"
                 : "+r"(c[0]), "+r"(c[1])
                 : "r"(a[0]), "r"(a[1]), "r"(a[2]), "r"(a[3]), "r"(b0), "r"(b1));
}
__device__ __forceinline__ uint32_t h2ex2(uint32_t x) {
    uint32_t r;
    asm("ex2.approx.f16x2 %0, %1;" : "=r"(r) : "r"(x));
    return r;
}
__device__ __forceinline__ uint32_t pack4_e4m3(float a0, float a1, float a2, float a3) {
    __nv_fp8x2_e4m3 lo(make_float2(a0, a1));
    __nv_fp8x2_e4m3 hi(make_float2(a2, a3));
    return (uint32_t)lo.__x | ((uint32_t)hi.__x << 16);
}
__device__ __forceinline__ float2 h2f2(uint32_t r) {
    return __half22float2(*reinterpret_cast<__half2*>(&r));
}

// ---------------- tiling (pitches in BYTES) -----------------------------------
#define BM 128
#define BN 256
#define CHUNK_B 128
#define NCHUNK  4
#define NSTAGE  3
#define APITCH 528           // 132 words == 4 mod 32 (ldsm conflict-free)
#define BPITCH 144           // 36 words  == 4 mod 32

#define A_BYTES       (BM * APITCH)                  // 67584
#define B_STAGE_BYTES (BN * BPITCH)                  // 36864
#define B_OFF         A_BYTES
#define SMEM_BYTES    (B_OFF + NSTAGE * B_STAGE_BYTES)   // 178176

// ======================= kernel 1: prep ======================================
__device__ __forceinline__ float block_reduce_128(float v, float* sbuf, int tid) {
    #pragma unroll
    for (int o = 16; o > 0; o >>= 1) v += __shfl_xor_sync(0xffffffffu, v, o);
    if ((tid & 31) == 0) sbuf[tid >> 5] = v;
    __syncthreads();
    float r = sbuf[0] + sbuf[1] + sbuf[2] + sbuf[3];
    __syncthreads();
    return r;
}

__global__ void prep_kernel(const float* __restrict__ x,
                            const int* __restrict__ labels_raw,
                            const float* __restrict__ W) {
    __shared__ float sbuf[4];
    const int tid = threadIdx.x;
    if (blockIdx.x < NROWS) {
        const int row = blockIdx.x;
        const float* xr = x + (size_t)row * DIM;
        float v[4]; float ss = 0.f;
        #pragma unroll
        for (int j = 0; j < 4; j++) { v[j] = xr[tid + 128*j]; ss += v[j]*v[j]; }
        ss = block_reduce_128(ss, sbuf, tid);
        float inv = rsqrtf(ss);
        #pragma unroll
        for (int j = 0; j < 4; j++)
            g_xn8[(size_t)row * DIM + tid + 128*j] =
                __nv_fp8_e4m3(v[j] * inv * XS).__x;

        bool is64 = (labels_raw[1] == 0 && labels_raw[3] == 0 &&
                     labels_raw[5] == 0 && labels_raw[7] == 0);
        int lab = is64 ? labels_raw[2*row] : labels_raw[row];
        const float* w = W + (size_t)lab * DIM;
        float dot = 0.f;
        #pragma unroll
        for (int j = 0; j < 4; j++) dot += v[j] * w[tid + 128*j];
        dot = block_reduce_128(dot, sbuf, tid);
        if (tid == 0) { g_target[row] = dot * inv; g_rowsum[row] = 0.f; }
    } else {
        if (blockIdx.x == NROWS && tid == 0) g_done = 0;
        const size_t base = ((size_t)(blockIdx.x - NROWS) * 128 + tid) * 16;
        const float4* src = reinterpret_cast<const float4*>(W + base);
        float4 v0 = src[0], v1 = src[1], v2 = src[2], v3 = src[3];
        uint4 o;
        o.x = pack4_e4m3(v0.x*WS, v0.y*WS, v0.z*WS, v0.w*WS);
        o.y = pack4_e4m3(v1.x*WS, v1.y*WS, v1.z*WS, v1.w*WS);
        o.z = pack4_e4m3(v2.x*WS, v2.y*WS, v2.z*WS, v2.w*WS);
        o.w = pack4_e4m3(v3.x*WS, v3.y*WS, v3.z*WS, v3.w*WS);
        *reinterpret_cast<uint4*>(g_WB8 + base) = o;
    }
}

// ======================= kernel 2: fp8-mma GEMM + exp rowsum =================
// 148 persistent CTAs, 512 threads / 16 warps.  Warp grid 4(m) x 4(n);
// warp tile 32x64.  3-stage cp.async pipeline, ONE barrier per 128B K-chunk.
// Epilogue: f16x2 ex2.approx on accumulator registers.
__device__ __forceinline__ void issue_b_chunk(uint32_t bs_dst, int bn, int k0, int tid) {
    #pragma unroll
    for (int i = 0; i < 4; i++) {
        int v = tid + THREADS * i;              // 2048 vectors = 256 rows x 8
        int r = v >> 3, kv = v & 7;
        int grow = bn * BN + r; if (grow >= NCLS) grow = NCLS - 1;
        const void* src = g_WB8 + ((size_t)grow * DIM + k0 + kv * 16);
        CP_ASYNC16(bs_dst + r * BPITCH + kv * 16, src);
    }
}

__global__ void __launch_bounds__(THREADS, 1) gemm_exp_kernel(float* __restrict__ out) {
    extern __shared__ __align__(16) char smem[];
    const uint32_t sb = smem_u32(smem);
    const int tid = threadIdx.x, wid = tid >> 5, lane = tid & 31;
    const int wm = wid & 3, wn = wid >> 2;
    const int cta = blockIdx.x;
    const int t0 = (cta * NTILES) / GRID;
    const int t1 = ((cta + 1) * NTILES) / GRID;

    const int lrow = lane & 15, lk16 = (lane >> 4) * 16;
    const uint32_t a_lane = sb + (wm * 32 + lrow) * APITCH + lk16;
    const uint32_t b_lane = sb + B_OFF + (wn * 64 + lrow) * BPITCH + lk16;

    int t = t0;
    while (t < t1) {
        const int bm = t / NBN;
        const int bn0 = t - bm * NBN;
        const int seg_end = min(t1, (bm + 1) * NBN);
        const int total = (seg_end - t) * NCHUNK;

        __syncthreads();   // prior-segment readers done before overwriting SMEM
        // ---- prologue: group0 = {A strip, chunk0}, group1 = {chunk1} ----
        const uint8_t* xa = g_xn8 + (size_t)bm * BM * DIM;
        #pragma unroll
        for (int i = 0; i < 8; i++) {
            int v = tid + THREADS * i;          // 4096 vectors = 128 rows x 32
            int r = v >> 5, kv = v & 31;
            CP_ASYNC16(sb + r * APITCH + kv * 16, xa + ((size_t)r * DIM + kv * 16));
        }
        issue_b_chunk(sb + B_OFF, bn0, 0, tid);
        CP_COMMIT();
        issue_b_chunk(sb + B_OFF + B_STAGE_BYTES, bn0, CHUNK_B, tid);
        CP_COMMIT();

        uint32_t acc[2][8][2];
        #pragma unroll
        for (int fm = 0; fm < 2; fm++)
            #pragma unroll
            for (int q = 0; q < 8; q++) { acc[fm][q][0] = 0u; acc[fm][q][1] = 0u; }
        float rsum[4] = {0.f, 0.f, 0.f, 0.f};
        int st_c = 0;   // stage of chunk j

        for (int j = 0; j < total; j++) {
            // chunk j arrival (thread-local), then block-wide publish; the same
            // barrier also retires chunk j-1's stage for the producer below.
            if (j + 1 < total) CP_WAIT1(); else CP_WAIT0();
            __syncthreads();
            const int jn2 = j + 2;
            if (jn2 < total) {
                int st2 = st_c + 2; if (st2 >= NSTAGE) st2 -= NSTAGE;
                issue_b_chunk(sb + B_OFF + st2 * B_STAGE_BYTES,
                              bn0 + (jn2 >> 2), (jn2 & 3) * CHUNK_B, tid);
                CP_COMMIT();
            }

            const int jc = j & 3;
            const uint32_t bch = b_lane + st_c * B_STAGE_BYTES;
            const uint32_t ach = a_lane + jc * CHUNK_B;
            #pragma unroll
            for (int ks = 0; ks < 4; ks++) {
                uint32_t Af[2][4], Bf[4][4];
                #pragma unroll
                for (int fm = 0; fm < 2; fm++)
                    ldsm4(Af[fm], ach + fm * 16 * APITCH + ks * 32);
                #pragma unroll
                for (int f = 0; f < 4; f++)
                    ldsm4(Bf[f], bch + f * 16 * BPITCH + ks * 32);
                #pragma unroll
                for (int fm = 0; fm < 2; fm++)
                    #pragma unroll
                    for (int f = 0; f < 4; f++) {
                        mma_fp8_h(acc[fm][2*f],   Af[fm], Bf[f][0], Bf[f][2]);
                        mma_fp8_h(acc[fm][2*f+1], Af[fm], Bf[f][1], Bf[f][3]);
                    }
            }

            // ---- per-tile epilogue ----
            if (jc == 3) {
                const int bn = bn0 + (j >> 2);
                if (bn != NBN - 1) {
                    // fast path: exp via ex2.approx.f16x2, accumulate in half2
                    const __half2 sc = __float2half2_rn(EXPS * LOG2E);
                    #pragma unroll
                    for (int fm = 0; fm < 2; fm++) {
                        #pragma unroll
                        for (int e = 0; e < 2; e++) {
                            __half2 hs = __float2half2_rn(0.f);
                            #pragma unroll
                            for (int q = 0; q < 8; q++) {
                                __half2 a = *reinterpret_cast<__half2*>(&acc[fm][q][e]);
                                __half2 m = __hmul2(a, sc);
                                uint32_t ex = h2ex2(*reinterpret_cast<uint32_t*>(&m));
                                hs = __hadd2(hs, *reinterpret_cast<__half2*>(&ex));
                                acc[fm][q][e] = 0u;
                            }
                            float2 fs = __half22float2(hs);
                            rsum[2*fm + e] += fs.x + fs.y;
                        }
                    }
                } else {
                    // tail tile: cols [99840, 100096), valid local col < 160
                    const int cb = wn * 64 + (lane & 3) * 2;
                    #pragma unroll
                    for (int fm = 0; fm < 2; fm++) {
                        float s0 = 0.f, s1 = 0.f;
                        #pragma unroll
                        for (int q = 0; q < 8; q++) {
                            int c0 = cb + q * 8;
                            float2 f0 = h2f2(acc[fm][q][0]);
                            float2 f1 = h2f2(acc[fm][q][1]);
                            if (c0 < 160) {
                                s0 += __expf(EXPS * f0.x);
                                s1 += __expf(EXPS * f1.x);
                            }
                            if (c0 + 1 < 160) {
                                s0 += __expf(EXPS * f0.y);
                                s1 += __expf(EXPS * f1.y);
                            }
                            acc[fm][q][0] = 0u; acc[fm][q][1] = 0u;
                        }
                        rsum[2*fm] += s0; rsum[2*fm+1] += s1;
                    }
                }
            }
            st_c++; if (st_c == NSTAGE) st_c = 0;
        }

        // ---- segment flush: quad-reduce, one atomic per row ----
        #pragma unroll
        for (int k = 0; k < 4; k++) {
            float v = rsum[k];
            v += __shfl_xor_sync(0xffffffffu, v, 1);
            v += __shfl_xor_sync(0xffffffffu, v, 2);
            if ((lane & 3) == 0) {
                int row = bm * BM + wm * 32 + (k >> 1) * 16 + (lane >> 2) + (k & 1) * 8;
                atomicAdd(&g_rowsum[row], v);
            }
        }
        t = seg_end;
    }

    // ---- last CTA computes the loss (finalize folded in) ----
    __threadfence();
    __syncthreads();
    __shared__ int slast;
    if (tid == 0) slast = (atomicAdd(&g_done, 1) == GRID - 1) ? 1 : 0;
    __syncthreads();
    if (slast) {
        __threadfence();
        double* sd = reinterpret_cast<double*>(smem);
        double local = 0.0;
        for (int i = tid; i < NROWS; i += THREADS) {
            float tg  = g_target[i];
            float num = S_SCALE * (tg - MARGIN);
            float denom = __expf(num) + g_rowsum[i] - __expf(S_SCALE * tg);
            local += (double)num - (double)__logf(denom);
        }
        sd[tid] = local;
        __syncthreads();
        for (int s = THREADS / 2; s > 0; s >>= 1) {
            if (tid < s) sd[tid] += sd[tid + s];
            __syncthreads();
        }
        if (tid == 0) out[0] = (float)(-sd[0] / (double)NROWS);
    }
}

// ======================= launch ==============================================
extern "C" void kernel_launch(void* const* d_in, const int* in_sizes, int n_in,
                              void* d_out, int out_size) {
    const float* x      = (const float*)d_in[0];
    const int*   labels = (const int*)d_in[1];
    const float* W      = (const float*)d_in[2];
    float* out = (float*)d_out;

    cudaFuncSetAttribute(gemm_exp_kernel,
                         cudaFuncAttributeMaxDynamicSharedMemorySize, SMEM_BYTES);

    prep_kernel<<<NROWS + 25000, 128>>>(x, labels, W);
    gemm_exp_kernel<<<GRID, THREADS, SMEM_BYTES>>>(out);
}

// round 14
// speedup vs baseline: 1.6517x; 1.0674x over previous
#include <cuda_runtime.h>
#include <cuda_bf16.h>
#include <cuda_fp16.h>
#include <cuda_fp8.h>
#include <cstdint>

#define NROWS 4096
#define DIM   512
#define NCLS  100000
#define NBM   32
#define NBN   782            // ceil(100000/128)
#define NTILES (NBM * NBN)   // 25024
#define GRID  296            // 2 CTAs per SM
#define THREADS 256
#define S_SCALE 30.0f
#define MARGIN  0.4f
#define XS 8.0f              // fp8 scale for xn
#define WS 32.0f             // fp8 scale for W
#define EXPS (S_SCALE / (XS * WS))
#define LOG2E 1.4426950408889634f

// ---------------- scratch (module-static device memory: allowed) ------------
__device__ __align__(128) uint8_t g_WB8[(size_t)NCLS * DIM];   // e4m3 W*32
__device__ __align__(128) uint8_t g_xn8[(size_t)NROWS * DIM];  // e4m3 xn*8
__device__ float g_rowsum[NROWS];
__device__ float g_target[NROWS];
__device__ int   g_done;

// ---------------- PTX helpers (sm_80/89-era, safe on sm_103) ----------------
__device__ __forceinline__ uint32_t smem_u32(const void* p) {
    uint32_t a;
    asm("{ .reg .u64 t; cvta.to.shared.u64 t, %1; cvt.u32.u64 %0, t; }" : "=r"(a) : "l"(p));
    return a;
}
#define CP_ASYNC16(dst, src) \
    asm volatile("cp.async.cg.shared.global [%0], [%1], 16;" :: "r"(dst), "l"(src) : "memory")
#define CP_COMMIT()  asm volatile("cp.async.commit_group;" ::: "memory")
#define CP_WAIT0()   asm volatile("cp.async.wait_group 0;" ::: "memory")

__device__ __forceinline__ void ldsm4(uint32_t* r, uint32_t addr) {
    asm volatile("ldmatrix.sync.aligned.m8n8.x4.shared.b16 {%0,%1,%2,%3}, [%4];"
                 : "=r"(r[0]), "=r"(r[1]), "=r"(r[2]), "=r"(r[3]) : "r"(addr));
}
__device__ __forceinline__ void mma_fp8_h(uint32_t* c, const uint32_t* a,
                                          uint32_t b0, uint32_t b1) {
    asm volatile("mma.sync.aligned.m16n8k32.row.col.f16.e4m3.e4m3.f16 "
                 "{%0,%1}, {%2,%3,%4,%5}, {%6,%7}, {%0,%1};"
                 : "+r"(c[0]), "+r"(c[1])
                 : "r"(a[0]), "r"(a[1]), "r"(a[2]), "r"(a[3]), "r"(b0), "r"(b1));
}
__device__ __forceinline__ uint32_t h2ex2(uint32_t x) {
    uint32_t r;
    asm("ex2.approx.f16x2 %0, %1;" : "=r"(r) : "r"(x));
    return r;
}
__device__ __forceinline__ uint32_t pack4_e4m3(float a0, float a1, float a2, float a3) {
    __nv_fp8x2_e4m3 lo(make_float2(a0, a1));
    __nv_fp8x2_e4m3 hi(make_float2(a2, a3));
    return (uint32_t)lo.__x | ((uint32_t)hi.__x << 16);
}
__device__ __forceinline__ float2 h2f2(uint32_t r) {
    return __half22float2(*reinterpret_cast<__half2*>(&r));
}

// ---------------- tiling (pitches in BYTES) -----------------------------------
#define BM 128
#define BN 128
#define CHUNK_B 128
#define NCHUNK  4
#define APITCH 528           // 132 words == 4 mod 32 (ldsm conflict-free)
#define BPITCH 144           // 36 words  == 4 mod 32

#define A_BYTES       (BM * APITCH)                  // 67584
#define B_STAGE_BYTES (BN * BPITCH)                  // 18432
#define B_OFF         A_BYTES
#define SMEM_BYTES    (B_OFF + 2 * B_STAGE_BYTES)    // 104448

// ======================= kernel 1: prep ======================================
__device__ __forceinline__ float block_reduce_128(float v, float* sbuf, int tid) {
    #pragma unroll
    for (int o = 16; o > 0; o >>= 1) v += __shfl_xor_sync(0xffffffffu, v, o);
    if ((tid & 31) == 0) sbuf[tid >> 5] = v;
    __syncthreads();
    float r = sbuf[0] + sbuf[1] + sbuf[2] + sbuf[3];
    __syncthreads();
    return r;
}

__global__ void prep_kernel(const float* __restrict__ x,
                            const int* __restrict__ labels_raw,
                            const float* __restrict__ W) {
    __shared__ float sbuf[4];
    const int tid = threadIdx.x;
    if (blockIdx.x < NROWS) {
        const int row = blockIdx.x;
        const float* xr = x + (size_t)row * DIM;
        float v[4]; float ss = 0.f;
        #pragma unroll
        for (int j = 0; j < 4; j++) { v[j] = xr[tid + 128*j]; ss += v[j]*v[j]; }
        ss = block_reduce_128(ss, sbuf, tid);
        float inv = rsqrtf(ss);
        #pragma unroll
        for (int j = 0; j < 4; j++)
            g_xn8[(size_t)row * DIM + tid + 128*j] =
                __nv_fp8_e4m3(v[j] * inv * XS).__x;

        bool is64 = (labels_raw[1] == 0 && labels_raw[3] == 0 &&
                     labels_raw[5] == 0 && labels_raw[7] == 0);
        int lab = is64 ? labels_raw[2*row] : labels_raw[row];
        const float* w = W + (size_t)lab * DIM;
        float dot = 0.f;
        #pragma unroll
        for (int j = 0; j < 4; j++) dot += v[j] * w[tid + 128*j];
        dot = block_reduce_128(dot, sbuf, tid);
        if (tid == 0) { g_target[row] = dot * inv; g_rowsum[row] = 0.f; }
    } else {
        if (blockIdx.x == NROWS && tid == 0) g_done = 0;
        const size_t base = ((size_t)(blockIdx.x - NROWS) * 128 + tid) * 16;
        const float4* src = reinterpret_cast<const float4*>(W + base);
        float4 v0 = src[0], v1 = src[1], v2 = src[2], v3 = src[3];
        uint4 o;
        o.x = pack4_e4m3(v0.x*WS, v0.y*WS, v0.z*WS, v0.w*WS);
        o.y = pack4_e4m3(v1.x*WS, v1.y*WS, v1.z*WS, v1.w*WS);
        o.z = pack4_e4m3(v2.x*WS, v2.y*WS, v2.z*WS, v2.w*WS);
        o.w = pack4_e4m3(v3.x*WS, v3.y*WS, v3.z*WS, v3.w*WS);
        *reinterpret_cast<uint4*>(g_WB8 + base) = o;
    }
}

// ======================= kernel 2: fp8-mma GEMM + exp rowsum =================
// 296 persistent CTAs (2/SM), 256 threads / 8 warps each.  Tile 128x128;
// warp grid 4(m) x 2(n), warp tile 32x64.  The co-resident sibling CTA hides
// barrier/epilogue bubbles.  2-stage cp.async pipeline, ONE barrier per chunk:
//   WAIT0 -> sync (publish chunk j, retire stage (j+1)&1) -> issue j+1 -> mma j
__device__ __forceinline__ void issue_b_chunk(uint32_t bs_dst, int bn, int k0, int tid) {
    #pragma unroll
    for (int i = 0; i < 4; i++) {
        int v = tid + THREADS * i;              // 1024 vectors = 128 rows x 8
        int r = v >> 3, kv = v & 7;
        int grow = bn * BN + r; if (grow >= NCLS) grow = NCLS - 1;
        const void* src = g_WB8 + ((size_t)grow * DIM + k0 + kv * 16);
        CP_ASYNC16(bs_dst + r * BPITCH + kv * 16, src);
    }
}

__global__ void __launch_bounds__(THREADS, 2) gemm_exp_kernel(float* __restrict__ out) {
    extern __shared__ __align__(16) char smem[];
    const uint32_t sb = smem_u32(smem);
    const int tid = threadIdx.x, wid = tid >> 5, lane = tid & 31;
    const int wm = wid & 3, wn = wid >> 2;     // 4(m) x 2(n)
    const int cta = blockIdx.x;
    const int t0 = (int)(((long long)cta * NTILES) / GRID);
    const int t1 = (int)(((long long)(cta + 1) * NTILES) / GRID);

    const int lrow = lane & 15, lk16 = (lane >> 4) * 16;
    const uint32_t a_lane = sb + (wm * 32 + lrow) * APITCH + lk16;
    const uint32_t b_lane = sb + B_OFF + (wn * 64 + lrow) * BPITCH + lk16;

    int t = t0;
    while (t < t1) {
        const int bm = t / NBN;
        const int bn0 = t - bm * NBN;
        const int seg_end = min(t1, (bm + 1) * NBN);
        const int total = (seg_end - t) * NCHUNK;

        __syncthreads();   // prior-segment readers done before overwriting SMEM
        // ---- prologue: one group = {A strip, chunk0} ----
        const uint8_t* xa = g_xn8 + (size_t)bm * BM * DIM;
        #pragma unroll
        for (int i = 0; i < 16; i++) {
            int v = tid + THREADS * i;          // 4096 vectors = 128 rows x 32
            int r = v >> 5, kv = v & 31;
            CP_ASYNC16(sb + r * APITCH + kv * 16, xa + ((size_t)r * DIM + kv * 16));
        }
        issue_b_chunk(sb + B_OFF, bn0, 0, tid);
        CP_COMMIT();

        uint32_t acc[2][8][2];
        #pragma unroll
        for (int fm = 0; fm < 2; fm++)
            #pragma unroll
            for (int q = 0; q < 8; q++) { acc[fm][q][0] = 0u; acc[fm][q][1] = 0u; }
        float rsum[4] = {0.f, 0.f, 0.f, 0.f};

        for (int j = 0; j < total; j++) {
            CP_WAIT0();        // my copies of chunk j (the only outstanding group)
            __syncthreads();   // publish chunk j; certify stage (j+1)&1 free
            const int jn = j + 1;
            if (jn < total) {
                issue_b_chunk(sb + B_OFF + (jn & 1) * B_STAGE_BYTES,
                              bn0 + (jn >> 2), (jn & 3) * CHUNK_B, tid);
                CP_COMMIT();
            }

            const int jc = j & 3;
            const uint32_t bch = b_lane + (j & 1) * B_STAGE_BYTES;
            const uint32_t ach = a_lane + jc * CHUNK_B;
            #pragma unroll
            for (int ks = 0; ks < 4; ks++) {
                uint32_t Af[2][4], Bf[4][4];
                #pragma unroll
                for (int fm = 0; fm < 2; fm++)
                    ldsm4(Af[fm], ach + fm * 16 * APITCH + ks * 32);
                #pragma unroll
                for (int f = 0; f < 4; f++)
                    ldsm4(Bf[f], bch + f * 16 * BPITCH + ks * 32);
                #pragma unroll
                for (int fm = 0; fm < 2; fm++)
                    #pragma unroll
                    for (int f = 0; f < 4; f++) {
                        mma_fp8_h(acc[fm][2*f],   Af[fm], Bf[f][0], Bf[f][2]);
                        mma_fp8_h(acc[fm][2*f+1], Af[fm], Bf[f][1], Bf[f][3]);
                    }
            }

            // ---- per-tile epilogue ----
            if (jc == 3) {
                const int bn = bn0 + (j >> 2);
                if (bn != NBN - 1) {
                    // fast path: exp via ex2.approx.f16x2, accumulate in half2
                    const __half2 sc = __float2half2_rn(EXPS * LOG2E);
                    #pragma unroll
                    for (int fm = 0; fm < 2; fm++) {
                        #pragma unroll
                        for (int e = 0; e < 2; e++) {
                            __half2 hs = __float2half2_rn(0.f);
                            #pragma unroll
                            for (int q = 0; q < 8; q++) {
                                __half2 a = *reinterpret_cast<__half2*>(&acc[fm][q][e]);
                                __half2 m = __hmul2(a, sc);
                                uint32_t ex = h2ex2(*reinterpret_cast<uint32_t*>(&m));
                                hs = __hadd2(hs, *reinterpret_cast<__half2*>(&ex));
                                acc[fm][q][e] = 0u;
                            }
                            float2 fs = __half22float2(hs);
                            rsum[2*fm + e] += fs.x + fs.y;
                        }
                    }
                } else {
                    // tail tile: cols [99968, 100096), valid local col < 32
                    const int cb = wn * 64 + (lane & 3) * 2;
                    #pragma unroll
                    for (int fm = 0; fm < 2; fm++) {
                        float s0 = 0.f, s1 = 0.f;
                        #pragma unroll
                        for (int q = 0; q < 8; q++) {
                            int c0 = cb + q * 8;
                            float2 f0 = h2f2(acc[fm][q][0]);
                            float2 f1 = h2f2(acc[fm][q][1]);
                            if (c0 < 32) {
                                s0 += __expf(EXPS * f0.x);
                                s1 += __expf(EXPS * f1.x);
                            }
                            if (c0 + 1 < 32) {
                                s0 += __expf(EXPS * f0.y);
                                s1 += __expf(EXPS * f1.y);
                            }
                            acc[fm][q][0] = 0u; acc[fm][q][1] = 0u;
                        }
                        rsum[2*fm] += s0; rsum[2*fm+1] += s1;
                    }
                }
            }
        }

        // ---- segment flush: quad-reduce, one atomic per row ----
        #pragma unroll
        for (int k = 0; k < 4; k++) {
            float v = rsum[k];
            v += __shfl_xor_sync(0xffffffffu, v, 1);
            v += __shfl_xor_sync(0xffffffffu, v, 2);
            if ((lane & 3) == 0) {
                int row = bm * BM + wm * 32 + (k >> 1) * 16 + (lane >> 2) + (k & 1) * 8;
                atomicAdd(&g_rowsum[row], v);
            }
        }
        t = seg_end;
    }

    // ---- last CTA computes the loss (finalize folded in) ----
    __threadfence();
    __syncthreads();
    __shared__ int slast;
    if (tid == 0) slast = (atomicAdd(&g_done, 1) == GRID - 1) ? 1 : 0;
    __syncthreads();
    if (slast) {
        __threadfence();
        double* sd = reinterpret_cast<double*>(smem);
        double local = 0.0;
        for (int i = tid; i < NROWS; i += THREADS) {
            float tg  = g_target[i];
            float num = S_SCALE * (tg - MARGIN);
            float denom = __expf(num) + g_rowsum[i] - __expf(S_SCALE * tg);
            local += (double)num - (double)__logf(denom);
        }
        sd[tid] = local;
        __syncthreads();
        for (int s = THREADS / 2; s > 0; s >>= 1) {
            if (tid < s) sd[tid] += sd[tid + s];
            __syncthreads();
        }
        if (tid == 0) out[0] = (float)(-sd[0] / (double)NROWS);
    }
}

// ======================= launch ==============================================
extern "C" void kernel_launch(void* const* d_in, const int* in_sizes, int n_in,
                              void* d_out, int out_size) {
    const float* x      = (const float*)d_in[0];
    const int*   labels = (const int*)d_in[1];
    const float* W      = (const float*)d_in[2];
    float* out = (float*)d_out;

    cudaFuncSetAttribute(gemm_exp_kernel,
                         cudaFuncAttributeMaxDynamicSharedMemorySize, SMEM_BYTES);

    prep_kernel<<<NROWS + 25000, 128>>>(x, labels, W);
    gemm_exp_kernel<<<GRID, THREADS, SMEM_BYTES>>>(out);
}

// round 15
// speedup vs baseline: 1.7107x; 1.0358x over previous
#include <cuda_runtime.h>
#include <cuda_bf16.h>
#include <cuda_fp16.h>
#include <cuda_fp8.h>
#include <cstdint>

#define NROWS 4096
#define DIM   512
#define NCLS  100000
#define NBM   32
#define NBN   782            // ceil(100000/128)
#define NTILES (NBM * NBN)   // 25024
#define GRID  296            // 2 CTAs per SM
#define THREADS 256
#define S_SCALE 30.0f
#define MARGIN  0.4f
#define XS 8.0f              // fp8 scale for xn
#define WS 32.0f             // fp8 scale for W
#define EXPS (S_SCALE / (XS * WS))
#define LOG2E 1.4426950408889634f

// ---------------- scratch (module-static device memory: allowed) ------------
__device__ __align__(128) uint8_t g_WB8[(size_t)NCLS * DIM];   // e4m3 W*32
__device__ __align__(128) uint8_t g_xn8[(size_t)NROWS * DIM];  // e4m3 xn*8
__device__ float g_rowsum[NROWS];
__device__ float g_target[NROWS];
__device__ int   g_done;

// ---------------- PTX helpers (sm_80/89-era, safe on sm_103) ----------------
__device__ __forceinline__ uint32_t smem_u32(const void* p) {
    uint32_t a;
    asm("{ .reg .u64 t; cvta.to.shared.u64 t, %1; cvt.u32.u64 %0, t; }" : "=r"(a) : "l"(p));
    return a;
}
#define CP_ASYNC16(dst, src) \
    asm volatile("cp.async.cg.shared.global [%0], [%1], 16;" :: "r"(dst), "l"(src) : "memory")
#define CP_COMMIT()  asm volatile("cp.async.commit_group;" ::: "memory")
#define CP_WAIT0()   asm volatile("cp.async.wait_group 0;" ::: "memory")

__device__ __forceinline__ void ldsm4(uint32_t* r, uint32_t addr) {
    asm volatile("ldmatrix.sync.aligned.m8n8.x4.shared.b16 {%0,%1,%2,%3}, [%4];"
                 : "=r"(r[0]), "=r"(r[1]), "=r"(r[2]), "=r"(r[3]) : "r"(addr));
}
__device__ __forceinline__ void mma_fp8_h(uint32_t* c, const uint32_t* a,
                                          uint32_t b0, uint32_t b1) {
    asm volatile("mma.sync.aligned.m16n8k32.row.col.f16.e4m3.e4m3.f16 "
                 "{%0,%1}, {%2,%3,%4,%5}, {%6,%7}, {%0,%1};"
                 : "+r"(c[0]), "+r"(c[1])
                 : "r"(a[0]), "r"(a[1]), "r"(a[2]), "r"(a[3]), "r"(b0), "r"(b1));
}
__device__ __forceinline__ uint32_t h2ex2(uint32_t x) {
    uint32_t r;
    asm("ex2.approx.f16x2 %0, %1;" : "=r"(r) : "r"(x));
    return r;
}
__device__ __forceinline__ uint32_t pack4_e4m3(float a0, float a1, float a2, float a3) {
    __nv_fp8x2_e4m3 lo(make_float2(a0, a1));
    __nv_fp8x2_e4m3 hi(make_float2(a2, a3));
    return (uint32_t)lo.__x | ((uint32_t)hi.__x << 16);
}
__device__ __forceinline__ float2 h2f2(uint32_t r) {
    return __half22float2(*reinterpret_cast<__half2*>(&r));
}

// ---------------- tiling (pitches in BYTES) -----------------------------------
#define BM 128
#define BN 128
#define CHUNK_B 128
#define NCHUNK  4
#define APITCH 528           // 132 words == 4 mod 32 (ldsm conflict-free)
#define BPITCH 144           // 36 words  == 4 mod 32

#define A_BYTES       (BM * APITCH)                  // 67584
#define B_STAGE_BYTES (BN * BPITCH)                  // 18432
#define B_OFF         A_BYTES
#define SMEM_BYTES    (B_OFF + 2 * B_STAGE_BYTES)    // 104448

// ======================= kernel 1: prep ======================================
__device__ __forceinline__ float block_reduce_128(float v, float* sbuf, int tid) {
    #pragma unroll
    for (int o = 16; o > 0; o >>= 1) v += __shfl_xor_sync(0xffffffffu, v, o);
    if ((tid & 31) == 0) sbuf[tid >> 5] = v;
    __syncthreads();
    float r = sbuf[0] + sbuf[1] + sbuf[2] + sbuf[3];
    __syncthreads();
    return r;
}

__global__ void prep_kernel(const float* __restrict__ x,
                            const int* __restrict__ labels_raw,
                            const float* __restrict__ W) {
    __shared__ float sbuf[4];
    const int tid = threadIdx.x;
    if (blockIdx.x < NROWS) {
        const int row = blockIdx.x;
        const float* xr = x + (size_t)row * DIM;
        float v[4]; float ss = 0.f;
        #pragma unroll
        for (int j = 0; j < 4; j++) { v[j] = xr[tid + 128*j]; ss += v[j]*v[j]; }
        ss = block_reduce_128(ss, sbuf, tid);
        float inv = rsqrtf(ss);
        #pragma unroll
        for (int j = 0; j < 4; j++)
            g_xn8[(size_t)row * DIM + tid + 128*j] =
                __nv_fp8_e4m3(v[j] * inv * XS).__x;

        bool is64 = (labels_raw[1] == 0 && labels_raw[3] == 0 &&
                     labels_raw[5] == 0 && labels_raw[7] == 0);
        int lab = is64 ? labels_raw[2*row] : labels_raw[row];
        const float* w = W + (size_t)lab * DIM;
        float dot = 0.f;
        #pragma unroll
        for (int j = 0; j < 4; j++) dot += v[j] * w[tid + 128*j];
        dot = block_reduce_128(dot, sbuf, tid);
        if (tid == 0) { g_target[row] = dot * inv; g_rowsum[row] = 0.f; }
    } else {
        if (blockIdx.x == NROWS && tid == 0) g_done = 0;
        const size_t base = ((size_t)(blockIdx.x - NROWS) * 128 + tid) * 16;
        const float4* src = reinterpret_cast<const float4*>(W + base);
        float4 v0 = src[0], v1 = src[1], v2 = src[2], v3 = src[3];
        uint4 o;
        o.x = pack4_e4m3(v0.x*WS, v0.y*WS, v0.z*WS, v0.w*WS);
        o.y = pack4_e4m3(v1.x*WS, v1.y*WS, v1.z*WS, v1.w*WS);
        o.z = pack4_e4m3(v2.x*WS, v2.y*WS, v2.z*WS, v2.w*WS);
        o.w = pack4_e4m3(v3.x*WS, v3.y*WS, v3.z*WS, v3.w*WS);
        *reinterpret_cast<uint4*>(g_WB8 + base) = o;
    }
}

// ======================= kernel 2: fp8-mma GEMM + exp rowsum =================
// 296 persistent CTAs (2/SM), 256 threads / 8 warps each.  Tile 128x128;
// warp grid 4(m) x 2(n), warp tile 32x64.  Sibling CTA hides barrier/epilogue
// bubbles.  Fully STATIC 4-chunk tile body: stage = c&1, all addresses are
// base+constant, single straight-line region for ptxas scheduling.
__device__ __forceinline__ void issue_b_chunk(uint32_t bs_dst, int bn, int k0, int tid) {
    #pragma unroll
    for (int i = 0; i < 4; i++) {
        int v = tid + THREADS * i;              // 1024 vectors = 128 rows x 8
        int r = v >> 3, kv = v & 7;
        int grow = bn * BN + r; if (grow >= NCLS) grow = NCLS - 1;
        const void* src = g_WB8 + ((size_t)grow * DIM + k0 + kv * 16);
        CP_ASYNC16(bs_dst + r * BPITCH + kv * 16, src);
    }
}

__global__ void __launch_bounds__(THREADS, 2) gemm_exp_kernel(float* __restrict__ out) {
    extern __shared__ __align__(16) char smem[];
    const uint32_t sb = smem_u32(smem);
    const int tid = threadIdx.x, wid = tid >> 5, lane = tid & 31;
    const int wm = wid & 3, wn = wid >> 2;     // 4(m) x 2(n)
    const int cta = blockIdx.x;
    const int t0 = (int)(((long long)cta * NTILES) / GRID);
    const int t1 = (int)(((long long)(cta + 1) * NTILES) / GRID);

    const int lrow = lane & 15, lk16 = (lane >> 4) * 16;
    const uint32_t a_lane = sb + (wm * 32 + lrow) * APITCH + lk16;
    const uint32_t b_lane = sb + B_OFF + (wn * 64 + lrow) * BPITCH + lk16;
    const __half2 sc = __float2half2_rn(EXPS * LOG2E);

    int t = t0;
    while (t < t1) {
        const int bm = t / NBN;
        const int bn0 = t - bm * NBN;
        const int seg_end = min(t1, (bm + 1) * NBN);
        const int nt = seg_end - t;

        __syncthreads();   // prior-segment readers done before overwriting SMEM
        // ---- prologue: one group = {A strip, chunk0 -> stage 0} ----
        const uint8_t* xa = g_xn8 + (size_t)bm * BM * DIM;
        #pragma unroll
        for (int i = 0; i < 16; i++) {
            int v = tid + THREADS * i;          // 4096 vectors = 128 rows x 32
            int r = v >> 5, kv = v & 31;
            CP_ASYNC16(sb + r * APITCH + kv * 16, xa + ((size_t)r * DIM + kv * 16));
        }
        issue_b_chunk(sb + B_OFF, bn0, 0, tid);
        CP_COMMIT();

        uint32_t acc[2][8][2];
        #pragma unroll
        for (int fm = 0; fm < 2; fm++)
            #pragma unroll
            for (int q = 0; q < 8; q++) { acc[fm][q][0] = 0u; acc[fm][q][1] = 0u; }
        float rsum[4] = {0.f, 0.f, 0.f, 0.f};

        for (int tt = 0; tt < nt; tt++) {
            const int bn = bn0 + tt;
            const bool last_tile = (tt == nt - 1);

            #pragma unroll
            for (int c = 0; c < NCHUNK; c++) {
                CP_WAIT0();        // chunk c of this tile has arrived
                __syncthreads();   // publish it; certify stage (c+1)&1 free
                if (c < 3) {
                    issue_b_chunk(sb + B_OFF + ((c + 1) & 1) * B_STAGE_BYTES,
                                  bn, (c + 1) * CHUNK_B, tid);
                    CP_COMMIT();
                } else if (!last_tile) {
                    issue_b_chunk(sb + B_OFF, bn + 1, 0, tid);   // stage 0
                    CP_COMMIT();
                }

                const uint32_t bch = b_lane + (c & 1) * B_STAGE_BYTES;
                const uint32_t ach = a_lane + c * CHUNK_B;
                #pragma unroll
                for (int ks = 0; ks < 4; ks++) {
                    uint32_t Af[2][4], Bf[4][4];
                    #pragma unroll
                    for (int fm = 0; fm < 2; fm++)
                        ldsm4(Af[fm], ach + fm * 16 * APITCH + ks * 32);
                    #pragma unroll
                    for (int f = 0; f < 4; f++)
                        ldsm4(Bf[f], bch + f * 16 * BPITCH + ks * 32);
                    #pragma unroll
                    for (int fm = 0; fm < 2; fm++)
                        #pragma unroll
                        for (int f = 0; f < 4; f++) {
                            mma_fp8_h(acc[fm][2*f],   Af[fm], Bf[f][0], Bf[f][2]);
                            mma_fp8_h(acc[fm][2*f+1], Af[fm], Bf[f][1], Bf[f][3]);
                        }
                }

                // ---- per-tile epilogue (static: only at c == 3) ----
                if (c == 3) {
                    if (bn != NBN - 1) {
                        #pragma unroll
                        for (int fm = 0; fm < 2; fm++) {
                            #pragma unroll
                            for (int e = 0; e < 2; e++) {
                                __half2 hs = __float2half2_rn(0.f);
                                #pragma unroll
                                for (int q = 0; q < 8; q++) {
                                    __half2 a = *reinterpret_cast<__half2*>(&acc[fm][q][e]);
                                    __half2 m = __hmul2(a, sc);
                                    uint32_t ex = h2ex2(*reinterpret_cast<uint32_t*>(&m));
                                    hs = __hadd2(hs, *reinterpret_cast<__half2*>(&ex));
                                    acc[fm][q][e] = 0u;
                                }
                                float2 fs = __half22float2(hs);
                                rsum[2*fm + e] += fs.x + fs.y;
                            }
                        }
                    } else {
                        // tail tile: cols [99968, 100096), valid local col < 32
                        const int cb = wn * 64 + (lane & 3) * 2;
                        #pragma unroll
                        for (int fm = 0; fm < 2; fm++) {
                            float s0 = 0.f, s1 = 0.f;
                            #pragma unroll
                            for (int q = 0; q < 8; q++) {
                                int c0 = cb + q * 8;
                                float2 f0 = h2f2(acc[fm][q][0]);
                                float2 f1 = h2f2(acc[fm][q][1]);
                                if (c0 < 32) {
                                    s0 += __expf(EXPS * f0.x);
                                    s1 += __expf(EXPS * f1.x);
                                }
                                if (c0 + 1 < 32) {
                                    s0 += __expf(EXPS * f0.y);
                                    s1 += __expf(EXPS * f1.y);
                                }
                                acc[fm][q][0] = 0u; acc[fm][q][1] = 0u;
                            }
                            rsum[2*fm] += s0; rsum[2*fm+1] += s1;
                        }
                    }
                }
            }
        }

        // ---- segment flush: quad-reduce, one atomic per row ----
        #pragma unroll
        for (int k = 0; k < 4; k++) {
            float v = rsum[k];
            v += __shfl_xor_sync(0xffffffffu, v, 1);
            v += __shfl_xor_sync(0xffffffffu, v, 2);
            if ((lane & 3) == 0) {
                int row = bm * BM + wm * 32 + (k >> 1) * 16 + (lane >> 2) + (k & 1) * 8;
                atomicAdd(&g_rowsum[row], v);
            }
        }
        t = seg_end;
    }

    // ---- last CTA computes the loss (finalize folded in) ----
    __threadfence();
    __syncthreads();
    __shared__ int slast;
    if (tid == 0) slast = (atomicAdd(&g_done, 1) == GRID - 1) ? 1 : 0;
    __syncthreads();
    if (slast) {
        __threadfence();
        double* sd = reinterpret_cast<double*>(smem);
        double local = 0.0;
        for (int i = tid; i < NROWS; i += THREADS) {
            float tg  = g_target[i];
            float num = S_SCALE * (tg - MARGIN);
            float denom = __expf(num) + g_rowsum[i] - __expf(S_SCALE * tg);
            local += (double)num - (double)__logf(denom);
        }
        sd[tid] = local;
        __syncthreads();
        for (int s = THREADS / 2; s > 0; s >>= 1) {
            if (tid < s) sd[tid] += sd[tid + s];
            __syncthreads();
        }
        if (tid == 0) out[0] = (float)(-sd[0] / (double)NROWS);
    }
}

// ======================= launch ==============================================
extern "C" void kernel_launch(void* const* d_in, const int* in_sizes, int n_in,
                              void* d_out, int out_size) {
    const float* x      = (const float*)d_in[0];
    const int*   labels = (const int*)d_in[1];
    const float* W      = (const float*)d_in[2];
    float* out = (float*)d_out;

    cudaFuncSetAttribute(gemm_exp_kernel,
                         cudaFuncAttributeMaxDynamicSharedMemorySize, SMEM_BYTES);

    prep_kernel<<<NROWS + 25000, 128>>>(x, labels, W);
    gemm_exp_kernel<<<GRID, THREADS, SMEM_BYTES>>>(out);
}